// round 2
// baseline (speedup 1.0000x reference)
#include <cuda_runtime.h>

// SubLSTM: T=512, B=64, I=H=1024, L=2, gates (i,o,z), fixed forget fg=sigmoid(f)
//   gates = sigmoid(x W^T + h R^T + bi + bh)
//   c' = c*fg + z - i ;  h' = sigmoid(c') - o
// Output: [out (T*B*H)][h0_fin][h1_fin][c0_fin][c1_fin]

#define T_STEPS 512
#define BATCH   64
#define HSZ     1024
#define G3      3072
#define TBH     (T_STEPS * BATCH * HSZ)
#define BH      (BATCH * HSZ)
#define NB      128          // persistent grid size (<=148 SMs -> co-resident)

// Device-global scratch (allocation-free rule)
__device__ float g_gx[(size_t)T_STEPS * BATCH * G3];   // [t][3072][64]  (Wx + bi + bh)
__device__ float g_h0[(size_t)T_STEPS * BATCH * HSZ];  // [t][b][h] layer-0 hidden seq
__device__ float g_htr[2 * HSZ * BATCH];               // ping-pong h, [h][b] transposed
__device__ unsigned g_arrive;                          // barrier counter (starts 0)
__device__ unsigned g_gen;                             // barrier generation

__device__ __forceinline__ float sigf(float x) { return 1.f / (1.f + __expf(-x)); }

// Software grid barrier: 128 co-resident CTAs. Release: per-thread fence +
// atomic arrive. Acquire: volatile poll on generation counter (L2-coherent).
__device__ __forceinline__ void grid_sync() {
    __threadfence();
    __syncthreads();
    if (threadIdx.x == 0) {
        unsigned gen = *(volatile unsigned*)&g_gen;
        unsigned t = atomicInc(&g_arrive, NB - 1);
        if (t == NB - 1) {
            __threadfence();
            *(volatile unsigned*)&g_gen = gen + 1;
        } else {
            while (*(volatile unsigned*)&g_gen == gen) { }
        }
        __threadfence();
    }
    __syncthreads();
}

// ---------------------------------------------------------------------------
// Big GEMM: gx[t][n][b] = (A[m=(t,b)][k] @ W[n][k]^T) + bi[n] + bh[n]
// 128x128 tile, BK=8, 256 threads, 8x8 microtile.
// ---------------------------------------------------------------------------
__global__ __launch_bounds__(256, 2) void gemm_bias_kernel(
    const float* __restrict__ A, const float* __restrict__ W,
    const float* __restrict__ bi, const float* __restrict__ bh,
    float* __restrict__ C, int M, int N, int K)
{
    __shared__ float As[8][128];
    __shared__ float Bs[8][128];
    const int tid  = threadIdx.x;
    const int tcol = tid & 15;
    const int trow = tid >> 4;
    const float* Ab = A + (size_t)blockIdx.y * 128 * K;
    const float* Wb = W + (size_t)blockIdx.x * 128 * K;
    const int lrow = tid >> 1;
    const int lk   = (tid & 1) * 4;

    float acc[8][8];
#pragma unroll
    for (int i = 0; i < 8; i++)
#pragma unroll
        for (int j = 0; j < 8; j++) acc[i][j] = 0.f;

    for (int k0 = 0; k0 < K; k0 += 8) {
        float4 a = *(const float4*)(Ab + (size_t)lrow * K + k0 + lk);
        float4 b = *(const float4*)(Wb + (size_t)lrow * K + k0 + lk);
        As[lk + 0][lrow] = a.x; As[lk + 1][lrow] = a.y;
        As[lk + 2][lrow] = a.z; As[lk + 3][lrow] = a.w;
        Bs[lk + 0][lrow] = b.x; Bs[lk + 1][lrow] = b.y;
        Bs[lk + 2][lrow] = b.z; Bs[lk + 3][lrow] = b.w;
        __syncthreads();
#pragma unroll
        for (int kk = 0; kk < 8; kk++) {
            float ra[8], rb[8];
            *(float4*)&ra[0] = *(const float4*)&As[kk][trow * 8];
            *(float4*)&ra[4] = *(const float4*)&As[kk][trow * 8 + 4];
            *(float4*)&rb[0] = *(const float4*)&Bs[kk][tcol * 8];
            *(float4*)&rb[4] = *(const float4*)&Bs[kk][tcol * 8 + 4];
#pragma unroll
            for (int i = 0; i < 8; i++)
#pragma unroll
                for (int j = 0; j < 8; j++) acc[i][j] += ra[i] * rb[j];
        }
        __syncthreads();
    }

    const int row0 = blockIdx.y * 128 + trow * 8;
    const int col0 = blockIdx.x * 128 + tcol * 8;
#pragma unroll
    for (int i = 0; i < 8; i++) {
        const int m  = row0 + i;
        const int tt = m >> 6;          // t
        const int b  = m & 63;          // batch
        float* Crow = C + ((size_t)tt * G3) * BATCH + b;
#pragma unroll
        for (int j = 0; j < 8; j++) {
            const int n = col0 + j;
            Crow[(size_t)n * BATCH] = acc[i][j] + bi[n] + bh[n];
        }
    }
}

// ---------------------------------------------------------------------------
// Persistent recurrence kernel: 128 CTAs x 256 threads, all 512 steps inside,
// software grid barrier between steps.
// CTA owns 8 H-columns (warp -> col), lane -> 2 batches, all 3 gates.
// h kept in ping-pong transposed buffer g_htr[2][h][b] (coalesced both ways).
// Cell state lives in registers for the whole sequence.
// ---------------------------------------------------------------------------
__global__ __launch_bounds__(256) void recurrent_kernel(
    const float* __restrict__ gx,   // [T][3072][64]
    const float* __restrict__ R,    // [3072][1024]
    const float* __restrict__ f,    // [1024]
    float* __restrict__ hb,         // [T][B][H] hidden sequence out
    float* __restrict__ hfin,       // [B][H]
    float* __restrict__ cfin)       // [B][H]
{
    __shared__ float hs[2][32][68];   // [buf][k][batch]
    __shared__ float ws[2][24][36];   // [buf][gate*8+col][k]

    const int tid  = threadIdx.x;
    const int warp = tid >> 5;
    const int lane = tid & 31;
    const int colbase = blockIdx.x * 8;
    const int col  = colbase + warp;

    // loader indices
    const int lkk = tid >> 3;           // 0..31 (k within tile)
    const int lbq = (tid & 7) * 8;      // batch quad base
    const int wr  = tid >> 3;           // 0..23 valid if tid<192 (R row idx)
    const int wkq = (tid & 7) * 4;      // k quad within tile
    const float* Rrow = R + (size_t)((wr >> 3) * HSZ + colbase + (wr & 7)) * HSZ;

    const float fg = sigf(f[col]);
    float c0 = 0.f, c1 = 0.f;

    float4 ph0, ph1, pw;
    const float* hp = g_htr;

#define LOAD_TILE(k0) do {                                                      \
        ph0 = __ldcg((const float4*)(hp + (size_t)((k0) + lkk) * BATCH + lbq)); \
        ph1 = __ldcg((const float4*)(hp + (size_t)((k0) + lkk) * BATCH + lbq + 4)); \
        if (tid < 192) pw = *(const float4*)(Rrow + (k0) + wkq);                \
    } while (0)

#define STS_TILE(bb) do {                                \
        *(float4*)&hs[bb][lkk][lbq]     = ph0;           \
        *(float4*)&hs[bb][lkk][lbq + 4] = ph1;           \
        if (tid < 192) *(float4*)&ws[bb][wr][wkq] = pw;  \
    } while (0)

#pragma unroll 1
    for (int t = 0; t < T_STEPS; t++) {
        float a00 = 0.f, a01 = 0.f, a10 = 0.f, a11 = 0.f, a20 = 0.f, a21 = 0.f;

        if (t > 0) {
            hp = g_htr + (size_t)((t - 1) & 1) * (HSZ * BATCH);
            LOAD_TILE(0);
            STS_TILE(0);
            __syncthreads();
#pragma unroll 1
            for (int tile = 0; tile < 32; tile++) {
                const int cur = tile & 1;
                if (tile < 31) LOAD_TILE((tile + 1) * 32);
#pragma unroll
                for (int kk0 = 0; kk0 < 32; kk0 += 4) {
                    float4 w0 = *(const float4*)&ws[cur][warp][kk0];
                    float4 w1 = *(const float4*)&ws[cur][8 + warp][kk0];
                    float4 w2 = *(const float4*)&ws[cur][16 + warp][kk0];
                    float wa0[4] = {w0.x, w0.y, w0.z, w0.w};
                    float wa1[4] = {w1.x, w1.y, w1.z, w1.w};
                    float wa2[4] = {w2.x, w2.y, w2.z, w2.w};
#pragma unroll
                    for (int j = 0; j < 4; j++) {
                        float2 hv = *(const float2*)&hs[cur][kk0 + j][2 * lane];
                        a00 += wa0[j] * hv.x; a01 += wa0[j] * hv.y;
                        a10 += wa1[j] * hv.x; a11 += wa1[j] * hv.y;
                        a20 += wa2[j] * hv.x; a21 += wa2[j] * hv.y;
                    }
                }
                if (tile < 31) STS_TILE(cur ^ 1);
                __syncthreads();
            }
        }

        // epilogue: gates, cell, hidden
        const float* gxt = gx + (size_t)t * G3 * BATCH + 2 * lane;
        float2 pi = __ldcg((const float2*)(gxt + (size_t)col * BATCH));
        float2 po = __ldcg((const float2*)(gxt + (size_t)(HSZ + col) * BATCH));
        float2 pz = __ldcg((const float2*)(gxt + (size_t)(2 * HSZ + col) * BATCH));
        float i0 = sigf(a00 + pi.x), i1 = sigf(a01 + pi.y);
        float o0 = sigf(a10 + po.x), o1 = sigf(a11 + po.y);
        float z0 = sigf(a20 + pz.x), z1 = sigf(a21 + pz.y);
        c0 = c0 * fg + z0 - i0;
        c1 = c1 * fg + z1 - i1;
        float hv0 = sigf(c0) - o0;
        float hv1 = sigf(c1) - o1;

        float* ht = g_htr + (size_t)(t & 1) * (HSZ * BATCH);
        __stcg((float2*)(ht + (size_t)col * BATCH + 2 * lane), make_float2(hv0, hv1));

        float* hbt = hb + (size_t)t * BH;
        __stcg(hbt + (size_t)(2 * lane) * HSZ + col, hv0);
        __stcg(hbt + (size_t)(2 * lane + 1) * HSZ + col, hv1);

        if (t == T_STEPS - 1) {
            hfin[(size_t)(2 * lane) * HSZ + col] = hv0;
            hfin[(size_t)(2 * lane + 1) * HSZ + col] = hv1;
            cfin[(size_t)(2 * lane) * HSZ + col] = c0;
            cfin[(size_t)(2 * lane + 1) * HSZ + col] = c1;
        }

        grid_sync();
    }
#undef LOAD_TILE
#undef STS_TILE
}

// ---------------------------------------------------------------------------
extern "C" void kernel_launch(void* const* d_in, const int* in_sizes, int n_in,
                              void* d_out, int out_size)
{
    const float* x   = (const float*)d_in[0];
    const float* W0  = (const float*)d_in[1];
    const float* R0  = (const float*)d_in[2];
    const float* bi0 = (const float*)d_in[3];
    const float* bh0 = (const float*)d_in[4];
    const float* f0  = (const float*)d_in[5];
    const float* W1  = (const float*)d_in[6];
    const float* R1  = (const float*)d_in[7];
    const float* bi1 = (const float*)d_in[8];
    const float* bh1 = (const float*)d_in[9];
    const float* f1  = (const float*)d_in[10];
    float* out = (float*)d_out;

    float *gx, *h0;
    cudaGetSymbolAddress((void**)&gx, g_gx);
    cudaGetSymbolAddress((void**)&h0, g_h0);

    const int M = T_STEPS * BATCH;      // 32768
    dim3 ggrid(G3 / 128, M / 128);      // (24, 256)

    // Layer 0
    gemm_bias_kernel<<<ggrid, 256>>>(x, W0, bi0, bh0, gx, M, G3, HSZ);
    recurrent_kernel<<<NB, 256>>>(gx, R0, f0, h0,
                                  out + TBH,              // h0 final
                                  out + TBH + 2 * BH);    // c0 final
    // Layer 1
    gemm_bias_kernel<<<ggrid, 256>>>(h0, W1, bi1, bh1, gx, M, G3, HSZ);
    recurrent_kernel<<<NB, 256>>>(gx, R1, f1, out,
                                  out + TBH + BH,         // h1 final
                                  out + TBH + 3 * BH);    // c1 final
}

// round 4
// speedup vs baseline: 1.1564x; 1.1564x over previous
#include <cuda_runtime.h>
#include <cstdint>

// SubLSTM: T=512, B=64, I=H=1024, L=2, gates (i,o,z), fixed forget fg=sigmoid(f)
//   gates = sigmoid(x W^T + h R^T + bi + bh)
//   c' = c*fg + z - i ;  h' = sigmoid(c') - o
// Output: [out (T*B*H)][h0_fin][h1_fin][c0_fin][c1_fin]

#define T_STEPS 512
#define BATCH   64
#define HSZ     1024
#define G3      3072
#define TBH     (T_STEPS * BATCH * HSZ)
#define BH      (BATCH * HSZ)
#define NB      128          // persistent grid size (<=148 SMs -> co-resident)

// Device-global scratch (allocation-free rule)
__device__ float g_gx[(size_t)T_STEPS * BATCH * G3];   // [t][3072][64]  (Wx + bi + bh)
__device__ float g_h0[(size_t)T_STEPS * BATCH * HSZ];  // [t][b][h] layer-0 hidden seq
__device__ float g_htr[2 * HSZ * BATCH];               // ping-pong h, [h][b] transposed
__device__ unsigned g_arrive;                          // barrier counter (starts 0)
__device__ unsigned g_gen;                             // barrier generation

__device__ __forceinline__ float sigf(float x) { return 1.f / (1.f + __expf(-x)); }

// ===================== PTX helpers (sm_80+ compatible) =====================
__device__ __forceinline__ uint32_t smem_u32(const void* p) {
    uint32_t a;
    asm("{ .reg .u64 t; cvta.to.shared.u64 t, %1; cvt.u32.u64 %0, t; }" : "=r"(a) : "l"(p));
    return a;
}
#define CP_ASYNC16(dst, src) \
    asm volatile("cp.async.ca.shared.global [%0], [%1], 16;" :: "r"(dst), "l"(src) : "memory")
#define CP_COMMIT() asm volatile("cp.async.commit_group;" ::: "memory")
#define CP_WAIT0()  asm volatile("cp.async.wait_group 0;" ::: "memory")

__device__ __forceinline__ uint32_t f2tf32(float x) {
    uint32_t u;
    asm("cvt.rna.tf32.f32 %0, %1;" : "=r"(u) : "f"(x));
    return u;
}
__device__ __forceinline__ void mma_tf32(float& d0, float& d1, float& d2, float& d3,
                                         uint32_t a0, uint32_t a1, uint32_t a2, uint32_t a3,
                                         uint32_t b0, uint32_t b1) {
    asm volatile("mma.sync.aligned.m16n8k8.row.col.f32.tf32.tf32.f32 "
                 "{%0,%1,%2,%3}, {%4,%5,%6,%7}, {%8,%9}, {%0,%1,%2,%3};"
                 : "+f"(d0), "+f"(d1), "+f"(d2), "+f"(d3)
                 : "r"(a0), "r"(a1), "r"(a2), "r"(a3), "r"(b0), "r"(b1));
}

// Software grid barrier: 128 co-resident CTAs.
__device__ __forceinline__ void grid_sync() {
    __threadfence();
    __syncthreads();
    if (threadIdx.x == 0) {
        unsigned gen = *(volatile unsigned*)&g_gen;
        unsigned t = atomicInc(&g_arrive, NB - 1);
        if (t == NB - 1) {
            __threadfence();
            *(volatile unsigned*)&g_gen = gen + 1;
        } else {
            while (*(volatile unsigned*)&g_gen == gen) { }
        }
        __threadfence();
    }
    __syncthreads();
}

// ---------------------------------------------------------------------------
// TF32 mma.sync GEMM: gx[t][n][b] = A[m=(t,b)][k] @ W[n][k]^T + bi[n] + bh[n]
// CTA 128x128, BK=32, 256 threads = 8 warps (wm 0..3, wn 0..1), warp tile 32x64.
// m16n8k8 fragments loaded by scalar LDS from padded smem ([128][36]).
// Epilogue stages 32-col chunks through smem for coalesced [t][n][b] stores.
// ---------------------------------------------------------------------------
#define SMPAD 36
__global__ __launch_bounds__(256, 2) void gemm_tf32_kernel(
    const float* __restrict__ A, const float* __restrict__ W,
    const float* __restrict__ bi, const float* __restrict__ bh,
    float* __restrict__ C)
{
    __shared__ float smA[128 * SMPAD];
    __shared__ float smB[128 * SMPAD];

    const int tid = threadIdx.x;
    const int wid = tid >> 5;
    const int lane = tid & 31;
    const int g   = lane >> 2;       // group id (0..7)
    const int tig = lane & 3;        // thread in group
    const int wm  = wid & 3;         // warp m index (0..3)
    const int wn  = wid >> 2;        // warp n index (0..1)
    const int m0  = blockIdx.y * 128;
    const int n0  = blockIdx.x * 128;

    const uint32_t sa = smem_u32(smA);
    const uint32_t sb = smem_u32(smB);

    float acc[2][8][4];
#pragma unroll
    for (int mt = 0; mt < 2; mt++)
#pragma unroll
        for (int nt = 0; nt < 8; nt++)
#pragma unroll
            for (int r = 0; r < 4; r++) acc[mt][nt][r] = 0.f;

    const int lrow = tid >> 3;       // 0..31 (row step 32 over i)
    const int lq   = tid & 7;        // float4 col

#pragma unroll 1
    for (int kt = 0; kt < HSZ / 32; kt++) {
        const int k0 = kt * 32;
#pragma unroll
        for (int i = 0; i < 4; i++) {
            const int row = lrow + i * 32;
            CP_ASYNC16(sa + (uint32_t)(row * SMPAD + lq * 4) * 4,
                       A + (size_t)(m0 + row) * HSZ + k0 + lq * 4);
            CP_ASYNC16(sb + (uint32_t)(row * SMPAD + lq * 4) * 4,
                       W + (size_t)(n0 + row) * HSZ + k0 + lq * 4);
        }
        CP_COMMIT();
        CP_WAIT0();
        __syncthreads();

#pragma unroll
        for (int s = 0; s < 4; s++) {
            const int kc = s * 8 + tig;
            uint32_t af[2][4];
#pragma unroll
            for (int mt = 0; mt < 2; mt++) {
                const int r0 = (wm * 32 + mt * 16 + g) * SMPAD;
                af[mt][0] = f2tf32(smA[r0 + kc]);
                af[mt][1] = f2tf32(smA[r0 + 8 * SMPAD + kc]);
                af[mt][2] = f2tf32(smA[r0 + kc + 4]);
                af[mt][3] = f2tf32(smA[r0 + 8 * SMPAD + kc + 4]);
            }
#pragma unroll
            for (int nt = 0; nt < 8; nt++) {
                const int nr = (wn * 64 + nt * 8 + g) * SMPAD;
                uint32_t b0 = f2tf32(smB[nr + kc]);
                uint32_t b1 = f2tf32(smB[nr + kc + 4]);
#pragma unroll
                for (int mt = 0; mt < 2; mt++)
                    mma_tf32(acc[mt][nt][0], acc[mt][nt][1], acc[mt][nt][2], acc[mt][nt][3],
                             af[mt][0], af[mt][1], af[mt][2], af[mt][3], b0, b1);
            }
        }
        __syncthreads();
    }

    // ---- Epilogue: stage 32-col chunks in smA, store coalesced to C[t][n][b]
    float* stage = smA;              // 128 x 33 floats fits in 128 x 36
    const int m_lane = tid & 63;
    const int n_off  = tid >> 6;
#pragma unroll 1
    for (int ci = 0; ci < 4; ci++) {
        if (wn == (ci >> 1)) {
            const int ntb = (ci & 1) * 4;
#pragma unroll
            for (int mt = 0; mt < 2; mt++) {
                const int r0 = wm * 32 + mt * 16 + g;
#pragma unroll
                for (int nn = 0; nn < 4; nn++) {
                    const int nt = ntb + nn;
                    const int nl = nn * 8 + 2 * tig;
                    stage[r0 * 33 + nl]           = acc[mt][nt][0];
                    stage[r0 * 33 + nl + 1]       = acc[mt][nt][1];
                    stage[(r0 + 8) * 33 + nl]     = acc[mt][nt][2];
                    stage[(r0 + 8) * 33 + nl + 1] = acc[mt][nt][3];
                }
            }
        }
        __syncthreads();
#pragma unroll
        for (int p = 0; p < 8; p++) {
            const int nlc = p * 4 + n_off;
            const int ng  = n0 + ci * 32 + nlc;
            const float bias = __ldg(bi + ng) + __ldg(bh + ng);
#pragma unroll
            for (int half = 0; half < 2; half++) {
                const int m  = m_lane + half * 64;
                const int mg = m0 + m;
                C[((size_t)(mg >> 6) * G3 + ng) * BATCH + (mg & 63)] =
                    stage[m * 33 + nlc] + bias;
            }
        }
        __syncthreads();
    }
}

// ---------------------------------------------------------------------------
// Persistent recurrence kernel (unchanged from passing round)
// ---------------------------------------------------------------------------
__global__ __launch_bounds__(256) void recurrent_kernel(
    const float* __restrict__ gx,   // [T][3072][64]
    const float* __restrict__ R,    // [3072][1024]
    const float* __restrict__ f,    // [1024]
    float* __restrict__ hb,         // [T][B][H] hidden sequence out
    float* __restrict__ hfin,       // [B][H]
    float* __restrict__ cfin)       // [B][H]
{
    __shared__ float hs[2][32][68];   // [buf][k][batch]
    __shared__ float ws[2][24][36];   // [buf][gate*8+col][k]

    const int tid  = threadIdx.x;
    const int warp = tid >> 5;
    const int lane = tid & 31;
    const int colbase = blockIdx.x * 8;
    const int col  = colbase + warp;

    const int lkk = tid >> 3;
    const int lbq = (tid & 7) * 8;
    const int wr  = tid >> 3;
    const int wkq = (tid & 7) * 4;
    const float* Rrow = R + (size_t)((wr >> 3) * HSZ + colbase + (wr & 7)) * HSZ;

    const float fg = sigf(f[col]);
    float c0 = 0.f, c1 = 0.f;

    float4 ph0, ph1, pw;
    const float* hp = g_htr;

#define LOAD_TILE(k0) do {                                                      \
        ph0 = __ldcg((const float4*)(hp + (size_t)((k0) + lkk) * BATCH + lbq)); \
        ph1 = __ldcg((const float4*)(hp + (size_t)((k0) + lkk) * BATCH + lbq + 4)); \
        if (tid < 192) pw = *(const float4*)(Rrow + (k0) + wkq);                \
    } while (0)

#define STS_TILE(bb) do {                                \
        *(float4*)&hs[bb][lkk][lbq]     = ph0;           \
        *(float4*)&hs[bb][lkk][lbq + 4] = ph1;           \
        if (tid < 192) *(float4*)&ws[bb][wr][wkq] = pw;  \
    } while (0)

#pragma unroll 1
    for (int t = 0; t < T_STEPS; t++) {
        float a00 = 0.f, a01 = 0.f, a10 = 0.f, a11 = 0.f, a20 = 0.f, a21 = 0.f;

        if (t > 0) {
            hp = g_htr + (size_t)((t - 1) & 1) * (HSZ * BATCH);
            LOAD_TILE(0);
            STS_TILE(0);
            __syncthreads();
#pragma unroll 1
            for (int tile = 0; tile < 32; tile++) {
                const int cur = tile & 1;
                if (tile < 31) LOAD_TILE((tile + 1) * 32);
#pragma unroll
                for (int kk0 = 0; kk0 < 32; kk0 += 4) {
                    float4 w0 = *(const float4*)&ws[cur][warp][kk0];
                    float4 w1 = *(const float4*)&ws[cur][8 + warp][kk0];
                    float4 w2 = *(const float4*)&ws[cur][16 + warp][kk0];
                    float wa0[4] = {w0.x, w0.y, w0.z, w0.w};
                    float wa1[4] = {w1.x, w1.y, w1.z, w1.w};
                    float wa2[4] = {w2.x, w2.y, w2.z, w2.w};
#pragma unroll
                    for (int j = 0; j < 4; j++) {
                        float2 hv = *(const float2*)&hs[cur][kk0 + j][2 * lane];
                        a00 += wa0[j] * hv.x; a01 += wa0[j] * hv.y;
                        a10 += wa1[j] * hv.x; a11 += wa1[j] * hv.y;
                        a20 += wa2[j] * hv.x; a21 += wa2[j] * hv.y;
                    }
                }
                if (tile < 31) STS_TILE(cur ^ 1);
                __syncthreads();
            }
        }

        const float* gxt = gx + (size_t)t * G3 * BATCH + 2 * lane;
        float2 pi = __ldcg((const float2*)(gxt + (size_t)col * BATCH));
        float2 po = __ldcg((const float2*)(gxt + (size_t)(HSZ + col) * BATCH));
        float2 pz = __ldcg((const float2*)(gxt + (size_t)(2 * HSZ + col) * BATCH));
        float i0 = sigf(a00 + pi.x), i1 = sigf(a01 + pi.y);
        float o0 = sigf(a10 + po.x), o1 = sigf(a11 + po.y);
        float z0 = sigf(a20 + pz.x), z1 = sigf(a21 + pz.y);
        c0 = c0 * fg + z0 - i0;
        c1 = c1 * fg + z1 - i1;
        float hv0 = sigf(c0) - o0;
        float hv1 = sigf(c1) - o1;

        float* ht = g_htr + (size_t)(t & 1) * (HSZ * BATCH);
        __stcg((float2*)(ht + (size_t)col * BATCH + 2 * lane), make_float2(hv0, hv1));

        float* hbt = hb + (size_t)t * BH;
        __stcg(hbt + (size_t)(2 * lane) * HSZ + col, hv0);
        __stcg(hbt + (size_t)(2 * lane + 1) * HSZ + col, hv1);

        if (t == T_STEPS - 1) {
            hfin[(size_t)(2 * lane) * HSZ + col] = hv0;
            hfin[(size_t)(2 * lane + 1) * HSZ + col] = hv1;
            cfin[(size_t)(2 * lane) * HSZ + col] = c0;
            cfin[(size_t)(2 * lane + 1) * HSZ + col] = c1;
        }

        grid_sync();
    }
#undef LOAD_TILE
#undef STS_TILE
}

// ---------------------------------------------------------------------------
extern "C" void kernel_launch(void* const* d_in, const int* in_sizes, int n_in,
                              void* d_out, int out_size)
{
    const float* x   = (const float*)d_in[0];
    const float* W0  = (const float*)d_in[1];
    const float* R0  = (const float*)d_in[2];
    const float* bi0 = (const float*)d_in[3];
    const float* bh0 = (const float*)d_in[4];
    const float* f0  = (const float*)d_in[5];
    const float* W1  = (const float*)d_in[6];
    const float* R1  = (const float*)d_in[7];
    const float* bi1 = (const float*)d_in[8];
    const float* bh1 = (const float*)d_in[9];
    const float* f1  = (const float*)d_in[10];
    float* out = (float*)d_out;

    float *gx, *h0;
    cudaGetSymbolAddress((void**)&gx, g_gx);
    cudaGetSymbolAddress((void**)&h0, g_h0);

    dim3 ggrid(G3 / 128, (T_STEPS * BATCH) / 128);   // (24, 256)

    // Layer 0
    gemm_tf32_kernel<<<ggrid, 256>>>(x, W0, bi0, bh0, gx);
    recurrent_kernel<<<NB, 256>>>(gx, R0, f0, h0,
                                  out + TBH,              // h0 final
                                  out + TBH + 2 * BH);    // c0 final
    // Layer 1
    gemm_tf32_kernel<<<ggrid, 256>>>(h0, W1, bi1, bh1, gx);
    recurrent_kernel<<<NB, 256>>>(gx, R1, f1, out,
                                  out + TBH + BH,         // h1 final
                                  out + TBH + 3 * BH);    // c1 final
}

// round 6
// speedup vs baseline: 2.9525x; 2.5533x over previous
#include <cuda_runtime.h>
#include <cstdint>

// SubLSTM: T=512, B=64, I=H=1024, L=2, gates (i,o,z), fixed forget fg=sigmoid(f)
//   gates = sigmoid(x W^T + h R^T + bi + bh)
//   c' = c*fg + z - i ;  h' = sigmoid(c') - o
// Output: [out (T*B*H)][h0_fin][h1_fin][c0_fin][c1_fin]

#define T_STEPS 512
#define BATCH   64
#define HSZ     1024
#define G3      3072
#define TBH     (T_STEPS * BATCH * HSZ)
#define BH      (BATCH * HSZ)
#define NB      128
#define HSLOT   (HSZ * BATCH)        // 65536 floats per ping-pong slot

// Device-global scratch (allocation-free rule)
__device__ float g_gx[(size_t)T_STEPS * BATCH * G3];   // [t][3072][64]
__device__ float g_h0[(size_t)T_STEPS * BATCH * HSZ];  // [t][b][h] layer-0 out
// h ping-pong in MMA fragment layout:
//   float idx = slot*65536 + (k>>4)*1024 + b*16 + (k&15)
__device__ float g_htr[2 * HSLOT];
__device__ unsigned g_arrive;
__device__ unsigned g_gen;

__device__ __forceinline__ float sigf(float x) { return 1.f / (1.f + __expf(-x)); }

// ===================== PTX helpers =====================
__device__ __forceinline__ uint32_t smem_u32(const void* p) {
    uint32_t a;
    asm("{ .reg .u64 t; cvta.to.shared.u64 t, %1; cvt.u32.u64 %0, t; }" : "=r"(a) : "l"(p));
    return a;
}
#define CP_ASYNC16(dst, src) \
    asm volatile("cp.async.ca.shared.global [%0], [%1], 16;" :: "r"(dst), "l"(src) : "memory")
#define CP_ASYNC_CG16(dst, src) \
    asm volatile("cp.async.cg.shared.global [%0], [%1], 16;" :: "r"(dst), "l"(src) : "memory")
#define CP_COMMIT() asm volatile("cp.async.commit_group;" ::: "memory")
#define CPWAIT(n)   asm volatile("cp.async.wait_group %0;" :: "n"(n) : "memory")

__device__ __forceinline__ uint32_t f2tf32(float x) {
    uint32_t u;
    asm("cvt.rna.tf32.f32 %0, %1;" : "=r"(u) : "f"(x));
    return u;
}
__device__ __forceinline__ float tf32f(float x) { return __uint_as_float(f2tf32(x)); }

__device__ __forceinline__ void mma_tf32(float& d0, float& d1, float& d2, float& d3,
                                         uint32_t a0, uint32_t a1, uint32_t a2, uint32_t a3,
                                         uint32_t b0, uint32_t b1) {
    asm volatile("mma.sync.aligned.m16n8k8.row.col.f32.tf32.tf32.f32 "
                 "{%0,%1,%2,%3}, {%4,%5,%6,%7}, {%8,%9}, {%0,%1,%2,%3};"
                 : "+f"(d0), "+f"(d1), "+f"(d2), "+f"(d3)
                 : "r"(a0), "r"(a1), "r"(a2), "r"(a3), "r"(b0), "r"(b1));
}
#define U(x) __float_as_uint(x)

// Software grid barrier: 128 co-resident CTAs.
__device__ __forceinline__ void grid_sync() {
    __threadfence();
    __syncthreads();
    if (threadIdx.x == 0) {
        unsigned gen = *(volatile unsigned*)&g_gen;
        unsigned t = atomicInc(&g_arrive, NB - 1);
        if (t == NB - 1) {
            __threadfence();
            *(volatile unsigned*)&g_gen = gen + 1;
        } else {
            while (*(volatile unsigned*)&g_gen == gen) { }
        }
        __threadfence();
    }
    __syncthreads();
}

// ---------------------------------------------------------------------------
// TF32 mma.sync GEMM (unchanged, passing)
// ---------------------------------------------------------------------------
#define SMPAD 36
__global__ __launch_bounds__(256, 2) void gemm_tf32_kernel(
    const float* __restrict__ A, const float* __restrict__ W,
    const float* __restrict__ bi, const float* __restrict__ bh,
    float* __restrict__ C)
{
    __shared__ float smA[128 * SMPAD];
    __shared__ float smB[128 * SMPAD];

    const int tid = threadIdx.x;
    const int wid = tid >> 5;
    const int lane = tid & 31;
    const int g   = lane >> 2;
    const int tig = lane & 3;
    const int wm  = wid & 3;
    const int wn  = wid >> 2;
    const int m0  = blockIdx.y * 128;
    const int n0  = blockIdx.x * 128;

    const uint32_t sa = smem_u32(smA);
    const uint32_t sb = smem_u32(smB);

    float acc[2][8][4];
#pragma unroll
    for (int mt = 0; mt < 2; mt++)
#pragma unroll
        for (int nt = 0; nt < 8; nt++)
#pragma unroll
            for (int r = 0; r < 4; r++) acc[mt][nt][r] = 0.f;

    const int lrow = tid >> 3;
    const int lq   = tid & 7;

#pragma unroll 1
    for (int kt = 0; kt < HSZ / 32; kt++) {
        const int k0 = kt * 32;
#pragma unroll
        for (int i = 0; i < 4; i++) {
            const int row = lrow + i * 32;
            CP_ASYNC16(sa + (uint32_t)(row * SMPAD + lq * 4) * 4,
                       A + (size_t)(m0 + row) * HSZ + k0 + lq * 4);
            CP_ASYNC16(sb + (uint32_t)(row * SMPAD + lq * 4) * 4,
                       W + (size_t)(n0 + row) * HSZ + k0 + lq * 4);
        }
        CP_COMMIT();
        CPWAIT(0);
        __syncthreads();

#pragma unroll
        for (int s = 0; s < 4; s++) {
            const int kc = s * 8 + tig;
            uint32_t af[2][4];
#pragma unroll
            for (int mt = 0; mt < 2; mt++) {
                const int r0 = (wm * 32 + mt * 16 + g) * SMPAD;
                af[mt][0] = f2tf32(smA[r0 + kc]);
                af[mt][1] = f2tf32(smA[r0 + 8 * SMPAD + kc]);
                af[mt][2] = f2tf32(smA[r0 + kc + 4]);
                af[mt][3] = f2tf32(smA[r0 + 8 * SMPAD + kc + 4]);
            }
#pragma unroll
            for (int nt = 0; nt < 8; nt++) {
                const int nr = (wn * 64 + nt * 8 + g) * SMPAD;
                uint32_t b0 = f2tf32(smB[nr + kc]);
                uint32_t b1 = f2tf32(smB[nr + kc + 4]);
#pragma unroll
                for (int mt = 0; mt < 2; mt++)
                    mma_tf32(acc[mt][nt][0], acc[mt][nt][1], acc[mt][nt][2], acc[mt][nt][3],
                             af[mt][0], af[mt][1], af[mt][2], af[mt][3], b0, b1);
            }
        }
        __syncthreads();
    }

    float* stage = smA;
    const int m_lane = tid & 63;
    const int n_off  = tid >> 6;
#pragma unroll 1
    for (int ci = 0; ci < 4; ci++) {
        if (wn == (ci >> 1)) {
            const int ntb = (ci & 1) * 4;
#pragma unroll
            for (int mt = 0; mt < 2; mt++) {
                const int r0 = wm * 32 + mt * 16 + g;
#pragma unroll
                for (int nn = 0; nn < 4; nn++) {
                    const int nt = ntb + nn;
                    const int nl = nn * 8 + 2 * tig;
                    stage[r0 * 33 + nl]           = acc[mt][nt][0];
                    stage[r0 * 33 + nl + 1]       = acc[mt][nt][1];
                    stage[(r0 + 8) * 33 + nl]     = acc[mt][nt][2];
                    stage[(r0 + 8) * 33 + nl + 1] = acc[mt][nt][3];
                }
            }
        }
        __syncthreads();
#pragma unroll
        for (int p = 0; p < 8; p++) {
            const int nlc = p * 4 + n_off;
            const int ng  = n0 + ci * 32 + nlc;
            const float bias = __ldg(bi + ng) + __ldg(bh + ng);
#pragma unroll
            for (int half = 0; half < 2; half++) {
                const int m  = m_lane + half * 64;
                const int mg = m0 + m;
                C[((size_t)(mg >> 6) * G3 + ng) * BATCH + (mg & 63)] =
                    stage[m * 33 + nlc] + bias;
            }
        }
        __syncthreads();
    }
}

// ---------------------------------------------------------------------------
// Persistent MMA recurrence: 128 CTAs x 128 threads (4 warps), R resident in
// smem (fragment order), h streamed via cp.async.cg (triple buffer), cell in
// registers. Warp wm owns batch rows {wm*16+g, +8}; CTA owns 8 h-cols.
// Dynamic smem: Rfrag 96KB + 3x32KB h = 192KB.
// ---------------------------------------------------------------------------
__global__ __launch_bounds__(128) void recurrent_kernel(
    const float* __restrict__ gx,   // [T][3072][64]
    const float* __restrict__ R,    // [3072][1024]
    const float* __restrict__ f,    // [1024]
    float* __restrict__ hb,         // [T][B][H]
    float* __restrict__ hfin,       // [B][H]
    float* __restrict__ cfin)       // [B][H]
{
    extern __shared__ float s_dyn[];
    float* Rf = s_dyn;              // 24576 floats: idx = ((k16*3+nt)*32+lane)*4+j
    float* Hs = s_dyn + 24576;      // 24576 floats: 3 bufs x 8192

    const int tid  = threadIdx.x;
    const int wm   = tid >> 5;
    const int lane = tid & 31;
    const int g    = lane >> 2;
    const int tig  = lane & 3;
    const int colbase = blockIdx.x * 8;

    // ---- Load R slice into fragment-ordered smem (tf32), once ----
    for (int v = tid; v < 6144; v += 128) {
        const int k16 = v / 96, rem = v % 96;
        const int nt = rem >> 5, ln = rem & 31;
        const int row = nt * HSZ + colbase + (ln >> 2);
        const int kk  = k16 * 16 + (ln & 3) * 4;
        float4 w = *(const float4*)(R + (size_t)row * HSZ + kk);
        float4 o;
        o.x = tf32f(w.x); o.y = tf32f(w.y); o.z = tf32f(w.z); o.w = tf32f(w.w);
        *(float4*)(Rf + (size_t)v * 4) = o;
    }
    __syncthreads();

    const int r0 = wm * 16 + g;
    const int r1 = r0 + 8;
    const int c0g = colbase + 2 * tig;
    const int c1g = c0g + 1;
    const float fg0 = sigf(__ldg(f + c0g));
    const float fg1 = sigf(__ldg(f + c1g));
    float cs00 = 0.f, cs01 = 0.f, cs10 = 0.f, cs11 = 0.f;

    const uint32_t hs_base = smem_u32(Hs);
    const int aoff = wm * 256 + lane * 4;           // A fragment float offset
    // g_htr write index base (fragment layout)
    const int wbase = (c0g >> 4) * 1024 + (c0g & 15);

    // Copy one 8192-float chunk: 128 threads x 16B, 16 wavefronts of 512 floats
#define ISSUE(cidx, buf) do {                                              \
        const float* s_ = hsrc + (cidx) * 8192 + tid * 4;                  \
        uint32_t d_ = hs_base + (uint32_t)((buf) * 8192 + tid * 4) * 4;    \
        _Pragma("unroll")                                                  \
        for (int j_ = 0; j_ < 16; j_++)                                    \
            CP_ASYNC_CG16(d_ + j_ * 512 * 4, s_ + j_ * 512);               \
        CP_COMMIT();                                                       \
    } while (0)

#pragma unroll 1
    for (int t = 0; t < T_STEPS; t++) {
        // gx preactivations (12 scalars, early issue)
        const float* gxt = gx + (size_t)t * G3 * BATCH;
        const float xi00 = __ldcg(gxt + (size_t)c0g * BATCH + r0);
        const float xi01 = __ldcg(gxt + (size_t)c1g * BATCH + r0);
        const float xi10 = __ldcg(gxt + (size_t)c0g * BATCH + r1);
        const float xi11 = __ldcg(gxt + (size_t)c1g * BATCH + r1);
        const float xo00 = __ldcg(gxt + (size_t)(HSZ + c0g) * BATCH + r0);
        const float xo01 = __ldcg(gxt + (size_t)(HSZ + c1g) * BATCH + r0);
        const float xo10 = __ldcg(gxt + (size_t)(HSZ + c0g) * BATCH + r1);
        const float xo11 = __ldcg(gxt + (size_t)(HSZ + c1g) * BATCH + r1);
        const float xz00 = __ldcg(gxt + (size_t)(2 * HSZ + c0g) * BATCH + r0);
        const float xz01 = __ldcg(gxt + (size_t)(2 * HSZ + c1g) * BATCH + r0);
        const float xz10 = __ldcg(gxt + (size_t)(2 * HSZ + c0g) * BATCH + r1);
        const float xz11 = __ldcg(gxt + (size_t)(2 * HSZ + c1g) * BATCH + r1);

        float a[3][4] = {{0.f,0.f,0.f,0.f},{0.f,0.f,0.f,0.f},{0.f,0.f,0.f,0.f}};

        if (t > 0) {
            const float* hsrc = g_htr + (size_t)((t - 1) & 1) * HSLOT;
            ISSUE(0, 0);
            ISSUE(1, 1);
#pragma unroll 1
            for (int c = 0; c < 8; c++) {
                if (c < 6) ISSUE(c + 2, (c + 2) % 3);
                if (c < 6)      CPWAIT(2);
                else if (c == 6) CPWAIT(1);
                else             CPWAIT(0);
                __syncthreads();
                const float* hbuf = Hs + (c % 3) * 8192 + aoff;
                const float4* rf4 = (const float4*)Rf + (size_t)(c * 24) * 32 + lane;
#pragma unroll
                for (int blk = 0; blk < 8; blk++) {
                    const float4 alo = *(const float4*)(hbuf + blk * 1024);
                    const float4 ahi = *(const float4*)(hbuf + blk * 1024 + 128);
#pragma unroll
                    for (int nt = 0; nt < 3; nt++) {
                        const float4 bf = rf4[(blk * 3 + nt) * 32];
                        mma_tf32(a[nt][0], a[nt][1], a[nt][2], a[nt][3],
                                 U(alo.x), U(ahi.x), U(alo.y), U(ahi.y),
                                 U(bf.x), U(bf.y));
                        mma_tf32(a[nt][0], a[nt][1], a[nt][2], a[nt][3],
                                 U(alo.z), U(ahi.z), U(alo.w), U(ahi.w),
                                 U(bf.z), U(bf.w));
                    }
                }
                __syncthreads();
            }
        }

        // ---- epilogue: gates, cell, hidden ----
        const float i00 = sigf(a[0][0] + xi00), i01 = sigf(a[0][1] + xi01);
        const float i10 = sigf(a[0][2] + xi10), i11 = sigf(a[0][3] + xi11);
        const float o00 = sigf(a[1][0] + xo00), o01 = sigf(a[1][1] + xo01);
        const float o10 = sigf(a[1][2] + xo10), o11 = sigf(a[1][3] + xo11);
        const float z00 = sigf(a[2][0] + xz00), z01 = sigf(a[2][1] + xz01);
        const float z10 = sigf(a[2][2] + xz10), z11 = sigf(a[2][3] + xz11);

        cs00 = cs00 * fg0 + z00 - i00;
        cs01 = cs01 * fg1 + z01 - i01;
        cs10 = cs10 * fg0 + z10 - i10;
        cs11 = cs11 * fg1 + z11 - i11;
        const float h00 = sigf(cs00) - o00;
        const float h01 = sigf(cs01) - o01;
        const float h10 = sigf(cs10) - o10;
        const float h11 = sigf(cs11) - o11;

        // h -> fragment-layout ping-pong (tf32-rounded mma input)
        float* slot = g_htr + (size_t)(t & 1) * HSLOT + wbase;
        __stcg((float2*)(slot + r0 * 16), make_float2(tf32f(h00), tf32f(h01)));
        __stcg((float2*)(slot + r1 * 16), make_float2(tf32f(h10), tf32f(h11)));

        // h -> sequence output [t][b][h] (full precision)
        float* hbt = hb + (size_t)t * BH;
        __stcg((float2*)(hbt + (size_t)r0 * HSZ + c0g), make_float2(h00, h01));
        __stcg((float2*)(hbt + (size_t)r1 * HSZ + c0g), make_float2(h10, h11));

        if (t == T_STEPS - 1) {
            *(float2*)(hfin + (size_t)r0 * HSZ + c0g) = make_float2(h00, h01);
            *(float2*)(hfin + (size_t)r1 * HSZ + c0g) = make_float2(h10, h11);
            *(float2*)(cfin + (size_t)r0 * HSZ + c0g) = make_float2(cs00, cs01);
            *(float2*)(cfin + (size_t)r1 * HSZ + c0g) = make_float2(cs10, cs11);
        }

        grid_sync();
    }
#undef ISSUE
}

// ---------------------------------------------------------------------------
extern "C" void kernel_launch(void* const* d_in, const int* in_sizes, int n_in,
                              void* d_out, int out_size)
{
    const float* x   = (const float*)d_in[0];
    const float* W0  = (const float*)d_in[1];
    const float* R0  = (const float*)d_in[2];
    const float* bi0 = (const float*)d_in[3];
    const float* bh0 = (const float*)d_in[4];
    const float* f0  = (const float*)d_in[5];
    const float* W1  = (const float*)d_in[6];
    const float* R1  = (const float*)d_in[7];
    const float* bi1 = (const float*)d_in[8];
    const float* bh1 = (const float*)d_in[9];
    const float* f1  = (const float*)d_in[10];
    float* out = (float*)d_out;

    float *gx, *h0;
    cudaGetSymbolAddress((void**)&gx, g_gx);
    cudaGetSymbolAddress((void**)&h0, g_h0);

    const int RSMEM = (24576 + 3 * 8192) * 4;   // 196608 B
    cudaFuncSetAttribute(recurrent_kernel,
                         cudaFuncAttributeMaxDynamicSharedMemorySize, RSMEM);

    dim3 ggrid(G3 / 128, (T_STEPS * BATCH) / 128);   // (24, 256)

    // Layer 0
    gemm_tf32_kernel<<<ggrid, 256>>>(x, W0, bi0, bh0, gx);
    recurrent_kernel<<<NB, 128, RSMEM>>>(gx, R0, f0, h0,
                                         out + TBH,              // h0 final
                                         out + TBH + 2 * BH);    // c0 final
    // Layer 1
    gemm_tf32_kernel<<<ggrid, 256>>>(h0, W1, bi1, bh1, gx);
    recurrent_kernel<<<NB, 128, RSMEM>>>(gx, R1, f1, out,
                                         out + TBH + BH,         // h1 final
                                         out + TBH + 3 * BH);    // c1 final
}

// round 7
// speedup vs baseline: 3.0353x; 1.0281x over previous
#include <cuda_runtime.h>
#include <cstdint>

// SubLSTM: T=512, B=64, I=H=1024, L=2, gates (i,o,z), fixed forget fg=sigmoid(f)
//   gates = sigmoid(x W^T + h R^T + bi + bh)
//   c' = c*fg + z - i ;  h' = sigmoid(c') - o
// Output: [out (T*B*H)][h0_fin][h1_fin][c0_fin][c1_fin]

#define T_STEPS 512
#define BATCH   64
#define HSZ     1024
#define G3      3072
#define TBH     (T_STEPS * BATCH * HSZ)
#define BH      (BATCH * HSZ)
#define NB      128
#define HSLOT   (HSZ * BATCH)        // 65536 floats per ping-pong slot

// Device-global scratch (allocation-free rule)
__device__ float g_gx[(size_t)T_STEPS * BATCH * G3];   // [t][3072][64]
__device__ float g_h0[(size_t)T_STEPS * BATCH * HSZ];  // [t][b][h] layer-0 out
// h ping-pong in MMA fragment layout:
//   float idx = slot*65536 + (k>>4)*1024 + b*16 + (k&15)
__device__ float g_htr[2 * HSLOT];
__device__ unsigned g_arrive;                 // legacy atomic barrier (init only)
__device__ unsigned g_gen;
__device__ volatile unsigned g_flags[NB * 32]; // per-CTA step flags, 128B stride

__device__ __forceinline__ float sigf(float x) { return 1.f / (1.f + __expf(-x)); }

// ===================== PTX helpers =====================
__device__ __forceinline__ uint32_t smem_u32(const void* p) {
    uint32_t a;
    asm("{ .reg .u64 t; cvta.to.shared.u64 t, %1; cvt.u32.u64 %0, t; }" : "=r"(a) : "l"(p));
    return a;
}
#define CP_ASYNC16(dst, src) \
    asm volatile("cp.async.ca.shared.global [%0], [%1], 16;" :: "r"(dst), "l"(src) : "memory")
#define CP_ASYNC_CG16(dst, src) \
    asm volatile("cp.async.cg.shared.global [%0], [%1], 16;" :: "r"(dst), "l"(src) : "memory")
#define CP_COMMIT() asm volatile("cp.async.commit_group;" ::: "memory")
#define CPWAIT(n)   asm volatile("cp.async.wait_group %0;" :: "n"(n) : "memory")

__device__ __forceinline__ uint32_t f2tf32(float x) {
    uint32_t u;
    asm("cvt.rna.tf32.f32 %0, %1;" : "=r"(u) : "f"(x));
    return u;
}
__device__ __forceinline__ float tf32f(float x) { return __uint_as_float(f2tf32(x)); }

__device__ __forceinline__ void mma_tf32(float& d0, float& d1, float& d2, float& d3,
                                         uint32_t a0, uint32_t a1, uint32_t a2, uint32_t a3,
                                         uint32_t b0, uint32_t b1) {
    asm volatile("mma.sync.aligned.m16n8k8.row.col.f32.tf32.tf32.f32 "
                 "{%0,%1,%2,%3}, {%4,%5,%6,%7}, {%8,%9}, {%0,%1,%2,%3};"
                 : "+f"(d0), "+f"(d1), "+f"(d2), "+f"(d3)
                 : "r"(a0), "r"(a1), "r"(a2), "r"(a3), "r"(b0), "r"(b1));
}
#define U(x) __float_as_uint(x)

// Legacy generation barrier (atomic). Used ONCE per launch to fence flag reset.
__device__ __forceinline__ void grid_sync_atomic() {
    __threadfence();
    __syncthreads();
    if (threadIdx.x == 0) {
        unsigned gen = *(volatile unsigned*)&g_gen;
        unsigned t = atomicInc(&g_arrive, NB - 1);
        if (t == NB - 1) {
            __threadfence();
            *(volatile unsigned*)&g_gen = gen + 1;
        } else {
            while (*(volatile unsigned*)&g_gen == gen) { }
        }
        __threadfence();
    }
    __syncthreads();
}

// Per-step flag barrier: each CTA writes its own flag (distinct L2 lines),
// thread i polls CTA i's flag. Requires blockDim.x >= NB.
__device__ __forceinline__ void flag_barrier(unsigned val) {
    __threadfence();
    __syncthreads();
    if (threadIdx.x == 0) g_flags[blockIdx.x * 32] = val;
    if (threadIdx.x < NB) {
        while (g_flags[threadIdx.x * 32] < val) { }
    }
    __threadfence();
    __syncthreads();
}

// ---------------------------------------------------------------------------
// TF32 mma.sync GEMM (unchanged, passing)
// ---------------------------------------------------------------------------
#define SMPAD 36
__global__ __launch_bounds__(256, 2) void gemm_tf32_kernel(
    const float* __restrict__ A, const float* __restrict__ W,
    const float* __restrict__ bi, const float* __restrict__ bh,
    float* __restrict__ C)
{
    __shared__ float smA[128 * SMPAD];
    __shared__ float smB[128 * SMPAD];

    const int tid = threadIdx.x;
    const int wid = tid >> 5;
    const int lane = tid & 31;
    const int g   = lane >> 2;
    const int tig = lane & 3;
    const int wm  = wid & 3;
    const int wn  = wid >> 2;
    const int m0  = blockIdx.y * 128;
    const int n0  = blockIdx.x * 128;

    const uint32_t sa = smem_u32(smA);
    const uint32_t sb = smem_u32(smB);

    float acc[2][8][4];
#pragma unroll
    for (int mt = 0; mt < 2; mt++)
#pragma unroll
        for (int nt = 0; nt < 8; nt++)
#pragma unroll
            for (int r = 0; r < 4; r++) acc[mt][nt][r] = 0.f;

    const int lrow = tid >> 3;
    const int lq   = tid & 7;

#pragma unroll 1
    for (int kt = 0; kt < HSZ / 32; kt++) {
        const int k0 = kt * 32;
#pragma unroll
        for (int i = 0; i < 4; i++) {
            const int row = lrow + i * 32;
            CP_ASYNC16(sa + (uint32_t)(row * SMPAD + lq * 4) * 4,
                       A + (size_t)(m0 + row) * HSZ + k0 + lq * 4);
            CP_ASYNC16(sb + (uint32_t)(row * SMPAD + lq * 4) * 4,
                       W + (size_t)(n0 + row) * HSZ + k0 + lq * 4);
        }
        CP_COMMIT();
        CPWAIT(0);
        __syncthreads();

#pragma unroll
        for (int s = 0; s < 4; s++) {
            const int kc = s * 8 + tig;
            uint32_t af[2][4];
#pragma unroll
            for (int mt = 0; mt < 2; mt++) {
                const int r0 = (wm * 32 + mt * 16 + g) * SMPAD;
                af[mt][0] = f2tf32(smA[r0 + kc]);
                af[mt][1] = f2tf32(smA[r0 + 8 * SMPAD + kc]);
                af[mt][2] = f2tf32(smA[r0 + kc + 4]);
                af[mt][3] = f2tf32(smA[r0 + 8 * SMPAD + kc + 4]);
            }
#pragma unroll
            for (int nt = 0; nt < 8; nt++) {
                const int nr = (wn * 64 + nt * 8 + g) * SMPAD;
                uint32_t b0 = f2tf32(smB[nr + kc]);
                uint32_t b1 = f2tf32(smB[nr + kc + 4]);
#pragma unroll
                for (int mt = 0; mt < 2; mt++)
                    mma_tf32(acc[mt][nt][0], acc[mt][nt][1], acc[mt][nt][2], acc[mt][nt][3],
                             af[mt][0], af[mt][1], af[mt][2], af[mt][3], b0, b1);
            }
        }
        __syncthreads();
    }

    float* stage = smA;
    const int m_lane = tid & 63;
    const int n_off  = tid >> 6;
#pragma unroll 1
    for (int ci = 0; ci < 4; ci++) {
        if (wn == (ci >> 1)) {
            const int ntb = (ci & 1) * 4;
#pragma unroll
            for (int mt = 0; mt < 2; mt++) {
                const int r0 = wm * 32 + mt * 16 + g;
#pragma unroll
                for (int nn = 0; nn < 4; nn++) {
                    const int nt = ntb + nn;
                    const int nl = nn * 8 + 2 * tig;
                    stage[r0 * 33 + nl]           = acc[mt][nt][0];
                    stage[r0 * 33 + nl + 1]       = acc[mt][nt][1];
                    stage[(r0 + 8) * 33 + nl]     = acc[mt][nt][2];
                    stage[(r0 + 8) * 33 + nl + 1] = acc[mt][nt][3];
                }
            }
        }
        __syncthreads();
#pragma unroll
        for (int p = 0; p < 8; p++) {
            const int nlc = p * 4 + n_off;
            const int ng  = n0 + ci * 32 + nlc;
            const float bias = __ldg(bi + ng) + __ldg(bh + ng);
#pragma unroll
            for (int half = 0; half < 2; half++) {
                const int m  = m_lane + half * 64;
                const int mg = m0 + m;
                C[((size_t)(mg >> 6) * G3 + ng) * BATCH + (mg & 63)] =
                    stage[m * 33 + nlc] + bias;
            }
        }
        __syncthreads();
    }
}

// ---------------------------------------------------------------------------
// Persistent MMA recurrence: 128 CTAs x 128 threads (4 warps), R resident in
// smem (fragment order), h streamed via cp.async.cg (triple buffer), cell in
// registers. Flag-based inter-step barrier.
// ---------------------------------------------------------------------------
__global__ __launch_bounds__(128) void recurrent_kernel(
    const float* __restrict__ gx,   // [T][3072][64]
    const float* __restrict__ R,    // [3072][1024]
    const float* __restrict__ f,    // [1024]
    float* __restrict__ hb,         // [T][B][H]
    float* __restrict__ hfin,       // [B][H]
    float* __restrict__ cfin)       // [B][H]
{
    extern __shared__ float s_dyn[];
    float* Rf = s_dyn;              // 24576 floats: idx = ((k16*3+nt)*32+lane)*4+j
    float* Hs = s_dyn + 24576;      // 24576 floats: 3 bufs x 8192

    const int tid  = threadIdx.x;
    const int wm   = tid >> 5;
    const int lane = tid & 31;
    const int g    = lane >> 2;
    const int tig  = lane & 3;
    const int colbase = blockIdx.x * 8;

    // Reset this CTA's step flag (replay safety); fenced by grid_sync_atomic.
    if (tid == 0) g_flags[blockIdx.x * 32] = 0;

    // ---- Load R slice into fragment-ordered smem (tf32), once ----
    for (int v = tid; v < 6144; v += 128) {
        const int k16 = v / 96, rem = v % 96;
        const int nt = rem >> 5, ln = rem & 31;
        const int row = nt * HSZ + colbase + (ln >> 2);
        const int kk  = k16 * 16 + (ln & 3) * 4;
        float4 w = *(const float4*)(R + (size_t)row * HSZ + kk);
        float4 o;
        o.x = tf32f(w.x); o.y = tf32f(w.y); o.z = tf32f(w.z); o.w = tf32f(w.w);
        *(float4*)(Rf + (size_t)v * 4) = o;
    }

    grid_sync_atomic();   // all flag resets + R loads visible chip-wide

    const int r0 = wm * 16 + g;
    const int r1 = r0 + 8;
    const int c0g = colbase + 2 * tig;
    const int c1g = c0g + 1;
    const float fg0 = sigf(__ldg(f + c0g));
    const float fg1 = sigf(__ldg(f + c1g));
    float cs00 = 0.f, cs01 = 0.f, cs10 = 0.f, cs11 = 0.f;

    const uint32_t hs_base = smem_u32(Hs);
    const int aoff = wm * 256 + lane * 4;           // A fragment float offset
    const int wbase = (c0g >> 4) * 1024 + (c0g & 15);

    // Copy one 8192-float chunk: 128 threads x 16B, 16 wavefronts of 512 floats
#define ISSUE(cidx, buf) do {                                              \
        const float* s_ = hsrc + (cidx) * 8192 + tid * 4;                  \
        uint32_t d_ = hs_base + (uint32_t)((buf) * 8192 + tid * 4) * 4;    \
        _Pragma("unroll")                                                  \
        for (int j_ = 0; j_ < 16; j_++)                                    \
            CP_ASYNC_CG16(d_ + j_ * 512 * 4, s_ + j_ * 512);               \
        CP_COMMIT();                                                       \
    } while (0)

#pragma unroll 1
    for (int t = 0; t < T_STEPS; t++) {
        // gx preactivations (12 scalars, early issue)
        const float* gxt = gx + (size_t)t * G3 * BATCH;
        const float xi00 = __ldcg(gxt + (size_t)c0g * BATCH + r0);
        const float xi01 = __ldcg(gxt + (size_t)c1g * BATCH + r0);
        const float xi10 = __ldcg(gxt + (size_t)c0g * BATCH + r1);
        const float xi11 = __ldcg(gxt + (size_t)c1g * BATCH + r1);
        const float xo00 = __ldcg(gxt + (size_t)(HSZ + c0g) * BATCH + r0);
        const float xo01 = __ldcg(gxt + (size_t)(HSZ + c1g) * BATCH + r0);
        const float xo10 = __ldcg(gxt + (size_t)(HSZ + c0g) * BATCH + r1);
        const float xo11 = __ldcg(gxt + (size_t)(HSZ + c1g) * BATCH + r1);
        const float xz00 = __ldcg(gxt + (size_t)(2 * HSZ + c0g) * BATCH + r0);
        const float xz01 = __ldcg(gxt + (size_t)(2 * HSZ + c1g) * BATCH + r0);
        const float xz10 = __ldcg(gxt + (size_t)(2 * HSZ + c0g) * BATCH + r1);
        const float xz11 = __ldcg(gxt + (size_t)(2 * HSZ + c1g) * BATCH + r1);

        float a[3][4] = {{0.f,0.f,0.f,0.f},{0.f,0.f,0.f,0.f},{0.f,0.f,0.f,0.f}};

        if (t > 0) {
            const float* hsrc = g_htr + (size_t)((t - 1) & 1) * HSLOT;
            ISSUE(0, 0);
            ISSUE(1, 1);
#pragma unroll 1
            for (int c = 0; c < 8; c++) {
                if (c == 7) CPWAIT(0); else CPWAIT(1);
                __syncthreads();                 // chunk c visible; prior reads of buf (c+2)%3 done
                if (c < 6) ISSUE(c + 2, (c + 2) % 3);
                const float* hbuf = Hs + (c % 3) * 8192 + aoff;
                const float4* rf4 = (const float4*)Rf + (size_t)(c * 24) * 32 + lane;
#pragma unroll
                for (int blk = 0; blk < 8; blk++) {
                    const float4 alo = *(const float4*)(hbuf + blk * 1024);
                    const float4 ahi = *(const float4*)(hbuf + blk * 1024 + 128);
#pragma unroll
                    for (int nt = 0; nt < 3; nt++) {
                        const float4 bf = rf4[(blk * 3 + nt) * 32];
                        mma_tf32(a[nt][0], a[nt][1], a[nt][2], a[nt][3],
                                 U(alo.x), U(ahi.x), U(alo.y), U(ahi.y),
                                 U(bf.x), U(bf.y));
                        mma_tf32(a[nt][0], a[nt][1], a[nt][2], a[nt][3],
                                 U(alo.z), U(ahi.z), U(alo.w), U(ahi.w),
                                 U(bf.z), U(bf.w));
                    }
                }
            }
        }

        // ---- epilogue: gates, cell, hidden ----
        const float i00 = sigf(a[0][0] + xi00), i01 = sigf(a[0][1] + xi01);
        const float i10 = sigf(a[0][2] + xi10), i11 = sigf(a[0][3] + xi11);
        const float o00 = sigf(a[1][0] + xo00), o01 = sigf(a[1][1] + xo01);
        const float o10 = sigf(a[1][2] + xo10), o11 = sigf(a[1][3] + xo11);
        const float z00 = sigf(a[2][0] + xz00), z01 = sigf(a[2][1] + xz01);
        const float z10 = sigf(a[2][2] + xz10), z11 = sigf(a[2][3] + xz11);

        cs00 = cs00 * fg0 + z00 - i00;
        cs01 = cs01 * fg1 + z01 - i01;
        cs10 = cs10 * fg0 + z10 - i10;
        cs11 = cs11 * fg1 + z11 - i11;
        const float h00 = sigf(cs00) - o00;
        const float h01 = sigf(cs01) - o01;
        const float h10 = sigf(cs10) - o10;
        const float h11 = sigf(cs11) - o11;

        // h -> fragment-layout ping-pong (tf32-rounded mma input)
        float* slot = g_htr + (size_t)(t & 1) * HSLOT + wbase;
        __stcg((float2*)(slot + r0 * 16), make_float2(tf32f(h00), tf32f(h01)));
        __stcg((float2*)(slot + r1 * 16), make_float2(tf32f(h10), tf32f(h11)));

        // h -> sequence output [t][b][h] (full precision)
        float* hbt = hb + (size_t)t * BH;
        __stcg((float2*)(hbt + (size_t)r0 * HSZ + c0g), make_float2(h00, h01));
        __stcg((float2*)(hbt + (size_t)r1 * HSZ + c0g), make_float2(h10, h11));

        if (t == T_STEPS - 1) {
            *(float2*)(hfin + (size_t)r0 * HSZ + c0g) = make_float2(h00, h01);
            *(float2*)(hfin + (size_t)r1 * HSZ + c0g) = make_float2(h10, h11);
            *(float2*)(cfin + (size_t)r0 * HSZ + c0g) = make_float2(cs00, cs01);
            *(float2*)(cfin + (size_t)r1 * HSZ + c0g) = make_float2(cs10, cs11);
        } else {
            flag_barrier((unsigned)(t + 1));
        }
    }
#undef ISSUE
}

// ---------------------------------------------------------------------------
extern "C" void kernel_launch(void* const* d_in, const int* in_sizes, int n_in,
                              void* d_out, int out_size)
{
    const float* x   = (const float*)d_in[0];
    const float* W0  = (const float*)d_in[1];
    const float* R0  = (const float*)d_in[2];
    const float* bi0 = (const float*)d_in[3];
    const float* bh0 = (const float*)d_in[4];
    const float* f0  = (const float*)d_in[5];
    const float* W1  = (const float*)d_in[6];
    const float* R1  = (const float*)d_in[7];
    const float* bi1 = (const float*)d_in[8];
    const float* bh1 = (const float*)d_in[9];
    const float* f1  = (const float*)d_in[10];
    float* out = (float*)d_out;

    float *gx, *h0;
    cudaGetSymbolAddress((void**)&gx, g_gx);
    cudaGetSymbolAddress((void**)&h0, g_h0);

    const int RSMEM = (24576 + 3 * 8192) * 4;   // 196608 B
    cudaFuncSetAttribute(recurrent_kernel,
                         cudaFuncAttributeMaxDynamicSharedMemorySize, RSMEM);

    dim3 ggrid(G3 / 128, (T_STEPS * BATCH) / 128);   // (24, 256)

    // Layer 0
    gemm_tf32_kernel<<<ggrid, 256>>>(x, W0, bi0, bh0, gx);
    recurrent_kernel<<<NB, 128, RSMEM>>>(gx, R0, f0, h0,
                                         out + TBH,              // h0 final
                                         out + TBH + 2 * BH);    // c0 final
    // Layer 1
    gemm_tf32_kernel<<<ggrid, 256>>>(h0, W1, bi1, bh1, gx);
    recurrent_kernel<<<NB, 128, RSMEM>>>(gx, R1, f1, out,
                                         out + TBH + BH,         // h1 final
                                         out + TBH + 3 * BH);    // c1 final
}

// round 9
// speedup vs baseline: 3.6179x; 1.1919x over previous
#include <cuda_runtime.h>
#include <cuda_fp16.h>
#include <cstdint>

// SubLSTM: T=512, B=64, I=H=1024, L=2, gates (i,o,z), fixed forget fg=sigmoid(f)
//   gates = sigmoid(x W^T + h R^T + bi + bh)
//   c' = c*fg + z - i ;  h' = sigmoid(c') - o
// Output: [out (T*B*H)][h0_fin][h1_fin][c0_fin][c1_fin]

#define T_STEPS 512
#define BATCH   64
#define HSZ     1024
#define G3      3072
#define TBH     (T_STEPS * BATCH * HSZ)
#define BH      (BATCH * HSZ)
#define NB      128
#define HSLOTH  (HSZ * BATCH)        // 65536 halves per ping-pong slot

// Device-global scratch (allocation-free rule)
__device__ float  g_gx[(size_t)T_STEPS * BATCH * G3];   // [t][3072][64]
__device__ float  g_h0[(size_t)T_STEPS * BATCH * HSZ];  // [t][b][h] layer-0 out
// h ping-pong, fp16, A-FRAGMENT order for m16n8k16:
//   half idx = kb*1024 + (b>>4)*256 + lane*8 + (hi*4 + hb8*2 + lo)
//   where kb=k>>4, lane=(b&7)*4+((k&7)>>1), hi=(k&15)>>3, hb8=(b>>3)&1, lo=k&1
__device__ __half g_htrh[2 * HSLOTH];
__device__ unsigned g_arrive;                 // legacy atomic barrier (init only)
__device__ unsigned g_gen;
__device__ volatile unsigned g_flags[NB * 32]; // per-CTA step flags, 128B stride

__device__ __forceinline__ float sigf(float x) { return 1.f / (1.f + __expf(-x)); }

// ===================== PTX helpers =====================
__device__ __forceinline__ uint32_t smem_u32(const void* p) {
    uint32_t a;
    asm("{ .reg .u64 t; cvta.to.shared.u64 t, %1; cvt.u32.u64 %0, t; }" : "=r"(a) : "l"(p));
    return a;
}
#define CP_ASYNC16(dst, src) \
    asm volatile("cp.async.ca.shared.global [%0], [%1], 16;" :: "r"(dst), "l"(src) : "memory")
#define CP_ASYNC_CG16(dst, src) \
    asm volatile("cp.async.cg.shared.global [%0], [%1], 16;" :: "r"(dst), "l"(src) : "memory")
#define CP_COMMIT() asm volatile("cp.async.commit_group;" ::: "memory")
#define CPWAIT(n)   asm volatile("cp.async.wait_group %0;" :: "n"(n) : "memory")

__device__ __forceinline__ uint32_t f2tf32(float x) {
    uint32_t u;
    asm("cvt.rna.tf32.f32 %0, %1;" : "=r"(u) : "f"(x));
    return u;
}
__device__ __forceinline__ void mma_tf32(float& d0, float& d1, float& d2, float& d3,
                                         uint32_t a0, uint32_t a1, uint32_t a2, uint32_t a3,
                                         uint32_t b0, uint32_t b1) {
    asm volatile("mma.sync.aligned.m16n8k8.row.col.f32.tf32.tf32.f32 "
                 "{%0,%1,%2,%3}, {%4,%5,%6,%7}, {%8,%9}, {%0,%1,%2,%3};"
                 : "+f"(d0), "+f"(d1), "+f"(d2), "+f"(d3)
                 : "r"(a0), "r"(a1), "r"(a2), "r"(a3), "r"(b0), "r"(b1));
}
__device__ __forceinline__ void mma_f16(float& d0, float& d1, float& d2, float& d3,
                                        uint32_t a0, uint32_t a1, uint32_t a2, uint32_t a3,
                                        uint32_t b0, uint32_t b1) {
    asm volatile("mma.sync.aligned.m16n8k16.row.col.f32.f16.f16.f32 "
                 "{%0,%1,%2,%3}, {%4,%5,%6,%7}, {%8,%9}, {%0,%1,%2,%3};"
                 : "+f"(d0), "+f"(d1), "+f"(d2), "+f"(d3)
                 : "r"(a0), "r"(a1), "r"(a2), "r"(a3), "r"(b0), "r"(b1));
}

// Legacy generation barrier (atomic). Used ONCE per launch to fence init.
__device__ __forceinline__ void grid_sync_atomic() {
    __threadfence();
    __syncthreads();
    if (threadIdx.x == 0) {
        unsigned gen = *(volatile unsigned*)&g_gen;
        unsigned t = atomicInc(&g_arrive, NB - 1);
        if (t == NB - 1) {
            __threadfence();
            *(volatile unsigned*)&g_gen = gen + 1;
        } else {
            while (*(volatile unsigned*)&g_gen == gen) { }
        }
        __threadfence();
    }
    __syncthreads();
}

// Per-step flag barrier: each CTA writes its own flag (distinct L2 lines),
// thread i polls CTA i's flag. Requires blockDim.x >= NB.
__device__ __forceinline__ void flag_barrier(unsigned val) {
    __threadfence();
    __syncthreads();
    if (threadIdx.x == 0) g_flags[blockIdx.x * 32] = val;
    if (threadIdx.x < NB) {
        while (g_flags[threadIdx.x * 32] < val) { }
    }
    __threadfence();
    __syncthreads();
}

// ---------------------------------------------------------------------------
// TF32 mma.sync GEMM (unchanged, passing)
// ---------------------------------------------------------------------------
#define SMPAD 36
__global__ __launch_bounds__(256, 2) void gemm_tf32_kernel(
    const float* __restrict__ A, const float* __restrict__ W,
    const float* __restrict__ bi, const float* __restrict__ bh,
    float* __restrict__ C)
{
    __shared__ float smA[128 * SMPAD];
    __shared__ float smB[128 * SMPAD];

    const int tid = threadIdx.x;
    const int wid = tid >> 5;
    const int lane = tid & 31;
    const int g   = lane >> 2;
    const int tig = lane & 3;
    const int wm  = wid & 3;
    const int wn  = wid >> 2;
    const int m0  = blockIdx.y * 128;
    const int n0  = blockIdx.x * 128;

    const uint32_t sa = smem_u32(smA);
    const uint32_t sb = smem_u32(smB);

    float acc[2][8][4];
#pragma unroll
    for (int mt = 0; mt < 2; mt++)
#pragma unroll
        for (int nt = 0; nt < 8; nt++)
#pragma unroll
            for (int r = 0; r < 4; r++) acc[mt][nt][r] = 0.f;

    const int lrow = tid >> 3;
    const int lq   = tid & 7;

#pragma unroll 1
    for (int kt = 0; kt < HSZ / 32; kt++) {
        const int k0 = kt * 32;
#pragma unroll
        for (int i = 0; i < 4; i++) {
            const int row = lrow + i * 32;
            CP_ASYNC16(sa + (uint32_t)(row * SMPAD + lq * 4) * 4,
                       A + (size_t)(m0 + row) * HSZ + k0 + lq * 4);
            CP_ASYNC16(sb + (uint32_t)(row * SMPAD + lq * 4) * 4,
                       W + (size_t)(n0 + row) * HSZ + k0 + lq * 4);
        }
        CP_COMMIT();
        CPWAIT(0);
        __syncthreads();

#pragma unroll
        for (int s = 0; s < 4; s++) {
            const int kc = s * 8 + tig;
            uint32_t af[2][4];
#pragma unroll
            for (int mt = 0; mt < 2; mt++) {
                const int r0 = (wm * 32 + mt * 16 + g) * SMPAD;
                af[mt][0] = f2tf32(smA[r0 + kc]);
                af[mt][1] = f2tf32(smA[r0 + 8 * SMPAD + kc]);
                af[mt][2] = f2tf32(smA[r0 + kc + 4]);
                af[mt][3] = f2tf32(smA[r0 + 8 * SMPAD + kc + 4]);
            }
#pragma unroll
            for (int nt = 0; nt < 8; nt++) {
                const int nr = (wn * 64 + nt * 8 + g) * SMPAD;
                uint32_t b0 = f2tf32(smB[nr + kc]);
                uint32_t b1 = f2tf32(smB[nr + kc + 4]);
#pragma unroll
                for (int mt = 0; mt < 2; mt++)
                    mma_tf32(acc[mt][nt][0], acc[mt][nt][1], acc[mt][nt][2], acc[mt][nt][3],
                             af[mt][0], af[mt][1], af[mt][2], af[mt][3], b0, b1);
            }
        }
        __syncthreads();
    }

    float* stage = smA;
    const int m_lane = tid & 63;
    const int n_off  = tid >> 6;
#pragma unroll 1
    for (int ci = 0; ci < 4; ci++) {
        if (wn == (ci >> 1)) {
            const int ntb = (ci & 1) * 4;
#pragma unroll
            for (int mt = 0; mt < 2; mt++) {
                const int r0 = wm * 32 + mt * 16 + g;
#pragma unroll
                for (int nn = 0; nn < 4; nn++) {
                    const int nt = ntb + nn;
                    const int nl = nn * 8 + 2 * tig;
                    stage[r0 * 33 + nl]           = acc[mt][nt][0];
                    stage[r0 * 33 + nl + 1]       = acc[mt][nt][1];
                    stage[(r0 + 8) * 33 + nl]     = acc[mt][nt][2];
                    stage[(r0 + 8) * 33 + nl + 1] = acc[mt][nt][3];
                }
            }
        }
        __syncthreads();
#pragma unroll
        for (int p = 0; p < 8; p++) {
            const int nlc = p * 4 + n_off;
            const int ng  = n0 + ci * 32 + nlc;
            const float bias = __ldg(bi + ng) + __ldg(bh + ng);
#pragma unroll
            for (int half = 0; half < 2; half++) {
                const int m  = m_lane + half * 64;
                const int mg = m0 + m;
                C[((size_t)(mg >> 6) * G3 + ng) * BATCH + (mg & 63)] =
                    stage[m * 33 + nlc] + bias;
            }
        }
        __syncthreads();
    }
}

// ---------------------------------------------------------------------------
// Persistent fp16 MMA recurrence: 128 CTAs x 128 threads (4 warps).
// All operands stored in EXACT m16n8k16 fragment order -> plain LDS loads.
//   R smem (B-frag): 8B per (k16-block kb, gate nt, lane): [(2t,n),(2t+1,n),
//     (2t+8,n),(2t+9,n)] at byte ((kb*3+nt)*32 + lane)*8.  48KB, loaded once.
//   h global (A-frag): see g_htrh comment. Consumer: linear cp.async chunks,
//     A = one LDS.128 per (warp, kb). Producer: one 8B store per thread.
// Smem: R 48KB + 3 x 16KB A bufs = 96KB. Cell state in registers.
// ---------------------------------------------------------------------------
__global__ __launch_bounds__(128) void recurrent_kernel(
    const float* __restrict__ gx,   // [T][3072][64]
    const float* __restrict__ R,    // [3072][1024]
    const float* __restrict__ f,    // [1024]
    float* __restrict__ hb,         // [T][B][H]
    float* __restrict__ hfin,       // [B][H]
    float* __restrict__ cfin)       // [B][H]
{
    extern __shared__ __align__(16) char s_dyn[];
    __half* Rsh = (__half*)s_dyn;            // 49152 B
    char*   Asm = s_dyn + 49152;             // 3 bufs x 16384 B

    const int tid  = threadIdx.x;
    const int wm   = tid >> 5;
    const int lane = tid & 31;
    const int g    = lane >> 2;
    const int tig  = lane & 3;
    const int colbase = blockIdx.x * 8;

    // Reset this CTA's step flag (replay safety); fenced by grid_sync_atomic.
    if (tid == 0) g_flags[blockIdx.x * 32] = 0;

    // ---- Load R slice -> B-fragment-order fp16 smem, once ----
    // v enumerates 24 rows x 256 float4: n = v>>8 (0..23), k = (v&255)*4
    for (int v = tid; v < 6144; v += 128) {
        const int n  = v >> 8;
        const int k  = (v & 255) * 4;
        const int nt = n >> 3, nloc = n & 7;
        const int row = nt * HSZ + colbase + nloc;
        float4 w = *(const float4*)(R + (size_t)row * HSZ + k);
        const int kb = k >> 4, kin = k & 15;
        const int t0 = (kin & 7) >> 1;     // fragment t of first pair
        const int hi = kin >> 3;
        // pos(halves) = ((kb*3+nt)*32 + nloc*4 + t)*4 + hi*2 + lo
        __half* base = Rsh + (((kb * 3 + nt) * 32 + nloc * 4) * 4 + hi * 2);
        *(__half2*)(base + (t0    ) * 4) = __floats2half2_rn(w.x, w.y);
        *(__half2*)(base + (t0 + 1) * 4) = __floats2half2_rn(w.z, w.w);
    }

    grid_sync_atomic();   // flag resets + R smem visible/done

    const int r0 = wm * 16 + g;
    const int r1 = r0 + 8;
    const int c0g = colbase + 2 * tig;
    const int c1g = c0g + 1;
    const float fg0 = sigf(__ldg(f + c0g));
    const float fg1 = sigf(__ldg(f + c1g));
    float cs00 = 0.f, cs01 = 0.f, cs10 = 0.f, cs11 = 0.f;

    const uint32_t hsA = smem_u32(Asm);
    // A fragment load address (bytes): + buf*16384 + blk*2048
    const uint32_t a_lm = hsA + (uint32_t)(wm * 512 + lane * 16);
    // h global write position (halves): producer's 4 values are contiguous
    //   p = kb*1024 + wm*256 + lane*8 + (bx&1)*4
    const int wp = (colbase >> 4) * 1024 + wm * 256 + lane * 8
                 + ((colbase >> 3) & 1) * 4;

    // Copy one 16KB chunk (8 k16-blocks), pure linear: 8 cp.async per thread
#define ISSUE(cidx, buf) do {                                                   \
        const char* s_ = (const char*)hsrc + (size_t)(cidx) * 16384 + tid * 16; \
        uint32_t d_ = hsA + (uint32_t)(buf) * 16384 + (uint32_t)(tid * 16);     \
        _Pragma("unroll")                                                       \
        for (int j_ = 0; j_ < 8; j_++)                                          \
            CP_ASYNC_CG16(d_ + j_ * 2048, s_ + j_ * 2048);                      \
        CP_COMMIT();                                                            \
    } while (0)

#pragma unroll 1
    for (int t = 0; t < T_STEPS; t++) {
        // gx preactivations (12 scalars, early issue)
        const float* gxt = gx + (size_t)t * G3 * BATCH;
        const float xi00 = __ldcg(gxt + (size_t)c0g * BATCH + r0);
        const float xi01 = __ldcg(gxt + (size_t)c1g * BATCH + r0);
        const float xi10 = __ldcg(gxt + (size_t)c0g * BATCH + r1);
        const float xi11 = __ldcg(gxt + (size_t)c1g * BATCH + r1);
        const float xo00 = __ldcg(gxt + (size_t)(HSZ + c0g) * BATCH + r0);
        const float xo01 = __ldcg(gxt + (size_t)(HSZ + c1g) * BATCH + r0);
        const float xo10 = __ldcg(gxt + (size_t)(HSZ + c0g) * BATCH + r1);
        const float xo11 = __ldcg(gxt + (size_t)(HSZ + c1g) * BATCH + r1);
        const float xz00 = __ldcg(gxt + (size_t)(2 * HSZ + c0g) * BATCH + r0);
        const float xz01 = __ldcg(gxt + (size_t)(2 * HSZ + c1g) * BATCH + r0);
        const float xz10 = __ldcg(gxt + (size_t)(2 * HSZ + c0g) * BATCH + r1);
        const float xz11 = __ldcg(gxt + (size_t)(2 * HSZ + c1g) * BATCH + r1);

        float a[3][4] = {{0.f,0.f,0.f,0.f},{0.f,0.f,0.f,0.f},{0.f,0.f,0.f,0.f}};

        if (t > 0) {
            const __half* hsrc = g_htrh + (size_t)((t - 1) & 1) * HSLOTH;
            ISSUE(0, 0);
            ISSUE(1, 1);
#pragma unroll 1
            for (int c = 0; c < 8; c++) {
                if (c == 7) CPWAIT(0); else CPWAIT(1);
                __syncthreads();                 // chunk c visible; buf (c+2)%3 free
                if (c < 6) ISSUE(c + 2, (c + 2) % 3);
                const uint32_t a_ch = a_lm + (uint32_t)(c % 3) * 16384;
#pragma unroll
                for (int blk = 0; blk < 8; blk++) {
                    uint4 Af;
                    asm volatile("ld.shared.v4.b32 {%0,%1,%2,%3}, [%4];"
                                 : "=r"(Af.x), "=r"(Af.y), "=r"(Af.z), "=r"(Af.w)
                                 : "r"(a_ch + (uint32_t)(blk * 2048)));
                    const int kbg = c * 8 + blk;
                    const uint2* bf = (const uint2*)((const char*)Rsh
                                      + (size_t)(kbg * 3) * 256 + lane * 8);
#pragma unroll
                    for (int nt = 0; nt < 3; nt++) {
                        const uint2 Bf = bf[nt * 32];   // +256B per gate
                        mma_f16(a[nt][0], a[nt][1], a[nt][2], a[nt][3],
                                Af.x, Af.y, Af.z, Af.w, Bf.x, Bf.y);
                    }
                }
            }
        }

        // ---- epilogue: gates, cell, hidden ----
        const float i00 = sigf(a[0][0] + xi00), i01 = sigf(a[0][1] + xi01);
        const float i10 = sigf(a[0][2] + xi10), i11 = sigf(a[0][3] + xi11);
        const float o00 = sigf(a[1][0] + xo00), o01 = sigf(a[1][1] + xo01);
        const float o10 = sigf(a[1][2] + xo10), o11 = sigf(a[1][3] + xo11);
        const float z00 = sigf(a[2][0] + xz00), z01 = sigf(a[2][1] + xz01);
        const float z10 = sigf(a[2][2] + xz10), z11 = sigf(a[2][3] + xz11);

        cs00 = cs00 * fg0 + z00 - i00;
        cs01 = cs01 * fg1 + z01 - i01;
        cs10 = cs10 * fg0 + z10 - i10;
        cs11 = cs11 * fg1 + z11 - i11;
        const float h00 = sigf(cs00) - o00;
        const float h01 = sigf(cs01) - o01;
        const float h10 = sigf(cs10) - o10;
        const float h11 = sigf(cs11) - o11;

        // h -> fp16 A-fragment ping-pong: 4 contiguous halves, one 8B store
        {
            __half2 p0 = __floats2half2_rn(h00, h01);   // (r0,c0),(r0,c1)
            __half2 p1 = __floats2half2_rn(h10, h11);   // (r1,c0),(r1,c1)
            uint2 pk;
            pk.x = *(unsigned*)&p0;
            pk.y = *(unsigned*)&p1;
            __half* slot = g_htrh + (size_t)(t & 1) * HSLOTH + wp;
            __stcg((uint2*)slot, pk);
        }

        // h -> sequence output [t][b][h] (full precision)
        float* hbt = hb + (size_t)t * BH;
        __stcg((float2*)(hbt + (size_t)r0 * HSZ + c0g), make_float2(h00, h01));
        __stcg((float2*)(hbt + (size_t)r1 * HSZ + c0g), make_float2(h10, h11));

        if (t == T_STEPS - 1) {
            *(float2*)(hfin + (size_t)r0 * HSZ + c0g) = make_float2(h00, h01);
            *(float2*)(hfin + (size_t)r1 * HSZ + c0g) = make_float2(h10, h11);
            *(float2*)(cfin + (size_t)r0 * HSZ + c0g) = make_float2(cs00, cs01);
            *(float2*)(cfin + (size_t)r1 * HSZ + c0g) = make_float2(cs10, cs11);
        } else {
            flag_barrier((unsigned)(t + 1));
        }
    }
#undef ISSUE
}

// ---------------------------------------------------------------------------
extern "C" void kernel_launch(void* const* d_in, const int* in_sizes, int n_in,
                              void* d_out, int out_size)
{
    const float* x   = (const float*)d_in[0];
    const float* W0  = (const float*)d_in[1];
    const float* R0  = (const float*)d_in[2];
    const float* bi0 = (const float*)d_in[3];
    const float* bh0 = (const float*)d_in[4];
    const float* f0  = (const float*)d_in[5];
    const float* W1  = (const float*)d_in[6];
    const float* R1  = (const float*)d_in[7];
    const float* bi1 = (const float*)d_in[8];
    const float* bh1 = (const float*)d_in[9];
    const float* f1  = (const float*)d_in[10];
    float* out = (float*)d_out;

    float *gx, *h0;
    cudaGetSymbolAddress((void**)&gx, g_gx);
    cudaGetSymbolAddress((void**)&h0, g_h0);

    const int RSMEM = 49152 + 3 * 16384;   // 98304 B
    cudaFuncSetAttribute(recurrent_kernel,
                         cudaFuncAttributeMaxDynamicSharedMemorySize, RSMEM);

    dim3 ggrid(G3 / 128, (T_STEPS * BATCH) / 128);   // (24, 256)

    // Layer 0
    gemm_tf32_kernel<<<ggrid, 256>>>(x, W0, bi0, bh0, gx);
    recurrent_kernel<<<NB, 128, RSMEM>>>(gx, R0, f0, h0,
                                         out + TBH,              // h0 final
                                         out + TBH + 2 * BH);    // c0 final
    // Layer 1
    gemm_tf32_kernel<<<ggrid, 256>>>(h0, W1, bi1, bh1, gx);
    recurrent_kernel<<<NB, 128, RSMEM>>>(gx, R1, f1, out,
                                         out + TBH + BH,         // h1 final
                                         out + TBH + 3 * BH);    // c1 final
}